// round 16
// baseline (speedup 1.0000x reference)
#include <cuda_runtime.h>
#include <cstdint>

// Problem constants (fixed by the reference)
#define BB 32
#define TT 256
#define NN 1536
#define NI 768

// Sim config: ONE CTA per batch, 384 threads, 4 neurons/thread.
#define TPB   384
#define NPT   4
#define NWORD 48                   // 1536 spike bits = 48 words
#define NTILE 24                   // ffprod column tiles of 64
#define FCOLS 64
#define FTPB  768                  // producer threads (24 warps/SM)

// exp constants, correctly rounded fp32
#define AR0 0.13533528323661270f   // exp(-2)    : rise tau 0.5 (syn0, syn2, FF)
#define AR1 0.60653065971263342f   // exp(-0.5)  : rise tau 2   (syn1)
#define AD0 0.60653065971263342f   // exp(-0.5)  : decay tau 2  (syn0, FF)
#define AD1 0.99004983374916805f   // exp(-0.01) : decay tau 100(syn1)
#define AD2 0.81873075307798186f   // exp(-0.2)  : decay tau 5  (syn2)

// ------------------------- device scratch (statics; no allocs) -------------
__device__ float d_Wsc[NN * NN];             // scaled W, rows in SORTED order
__device__ float d_WFsc[NI * NN];            // weights_FF * sfF[ct[m]]
__device__ float d_IF[(size_t)BB * TT * NN]; // FF drive (produced concurrently)
__device__ int   d_ffcnt[BB * TT];           // input spike counts per (b,t)
__device__ int   d_fflist[BB * TT][NI];      // byte offsets j*NN*4
__device__ int   d_perm[NN];                 // n -> sorted row position
__device__ int   d_NA;                       // #type-0 neurons
__device__ int   d_wm[BB][NTILE];            // FF progress watermarks (in t)

// ------------------------- packed f32x2 helpers -----------------------------
typedef unsigned long long u64;
__device__ __forceinline__ u64 pk2(float lo, float hi) {
    u64 r; asm("mov.b64 %0, {%1,%2};" : "=l"(r) : "f"(lo), "f"(hi)); return r;
}
__device__ __forceinline__ void upk2(float& lo, float& hi, u64 v) {
    asm("mov.b64 {%0,%1}, %2;" : "=f"(lo), "=f"(hi) : "l"(v));
}
__device__ __forceinline__ u64 fma2(u64 a, u64 b, u64 c) {
    u64 d; asm("fma.rn.f32x2 %0, %1, %2, %3;" : "=l"(d) : "l"(a), "l"(b), "l"(c));
    return d;
}
__device__ __forceinline__ u64 add2(u64 a, u64 b) {
    u64 d; asm("add.rn.f32x2 %0, %1, %2;" : "=l"(d) : "l"(a), "l"(b)); return d;
}
__device__ __forceinline__ u64 mul2(u64 a, u64 b) {
    u64 d; asm("mul.rn.f32x2 %0, %1, %2;" : "=l"(d) : "l"(a), "l"(b)); return d;
}

// --------- permutation (warp 0) + watermark reset, 256 threads --------------
// msave[48] costs ~100 regs/thread: 256 threads x 100 = 26K regs -> safe.
// (768-thread launches of this kernel exceed the register file: rounds 13/14.)
__global__ void __launch_bounds__(256) perm_k(const int* __restrict__ ct) {
    int tid = threadIdx.x;
    if (tid < BB * NTILE) ((int*)d_wm)[tid] = 0;   // watermark reset
    if (tid >= BB * NTILE - 256 && tid < 256) { }  // (no-op; single block)
    for (int i = tid + 256; i < BB * NTILE; i += 256) ((int*)d_wm)[i] = 0;
    if (tid >= 32) return;                          // warp 0: permutation
    int lane = tid;
    unsigned lt = (1u << lane) - 1u;
    unsigned msave[NWORD];
    int NAtot = 0;
#pragma unroll
    for (int w = 0; w < NWORD; w++) {
        int c = ct[w * 32 + lane];
        unsigned m = __ballot_sync(0xFFFFFFFFu, c == 0);
        msave[w] = m;
        NAtot += __popc(m);
    }
    int cA = 0, cB = 0;
#pragma unroll
    for (int w = 0; w < NWORD; w++) {
        unsigned m = msave[w];
        int is0 = (m >> lane) & 1;
        int p = is0 ? (cA + __popc(m & lt))
                    : (NAtot + cB + __popc((~m) & lt));
        d_perm[w * 32 + lane] = p;
        cA += __popc(m);
        cB += 32 - __popc(m);
    }
    if (lane == 0) d_NA = NAtot;
}

// ------------------------- FF weight scaling ---------------------------------
__global__ void scaleWF_k(const float4* __restrict__ wff,
                          const float* __restrict__ sff,
                          const int* __restrict__ ct) {
    const int F4 = (NI * NN) / 4;
    int r = blockIdx.x * 256 + threadIdx.x;
    if (r < F4) {
        int i4 = r * 4;
        int m = i4 % NN;
        int4 cm = *(const int4*)(ct + m);
        float4 v = wff[r];
        v.x *= sff[cm.x];
        v.y *= sff[cm.y];
        v.z *= sff[cm.z];
        v.w *= sff[cm.w];
        *(float4*)&d_WFsc[i4] = v;
    }
}

// ------------------------- recurrent weight scaling (rows permuted) --------
__global__ void scaleW_k(const float4* __restrict__ w,
                         const float* __restrict__ sf,
                         const int* __restrict__ ct) {
    const int T4 = (NN * NN) / 4;
    int idx = blockIdx.x * 256 + threadIdx.x;
    if (idx < T4) {
        int i4 = idx * 4;
        int n = i4 / NN, m = i4 % NN;
        int4 cm = *(const int4*)(ct + m);
        int cn = ct[n] * 2;
        float4 v = w[idx];
        v.x *= sf[cn + cm.x];
        v.y *= sf[cn + cm.y];
        v.z *= sf[cn + cm.z];
        v.w *= sf[cn + cm.w];
        int pn = d_perm[n];                       // sorted row placement
        *(float4*)&d_Wsc[pn * NN + m] = v;
    }
}

// ------------------------- FF spike lists (ballot-ordered, byte offsets) ---
__global__ void ffl_k(const float* __restrict__ inp) {
    int bt = blockIdx.x * 4 + (threadIdx.x >> 5); // 4 (b,t) rows per block
    int lane = threadIdx.x & 31;
    const float* row = inp + (size_t)bt * NI;
    int cnt = 0;
    for (int base = 0; base < NI; base += 32) {
        float v = row[base + lane];
        unsigned m = __ballot_sync(0xFFFFFFFFu, v > 0.5f);
        if (v > 0.5f) {
            int p = cnt + __popc(m & ((1u << lane) - 1u));
            d_fflist[bt][p] = (base + lane) * NN * 4;   // byte offset of row
        }
        cnt += __popc(m);
    }
    if (lane == 0) d_ffcnt[bt] = cnt;
}

// ------------------------- FF drive producer (1 CTA per SM, 1 tile) ---------
// Grid = (batch-octet 0..3, tile 0..23) = 96 CTAs; with 32 sim CTAs = 128
// <= 148 SMs -> one CTA per SM, each owning ONE 196KB L1-resident slab.
// List entries are loaded ONCE per 32 by lane ell and broadcast via shfl
// (kills the per-entry uniform L1 wavefront); 4-wide unrolled accumulate
// keeps 4 weight loads + 4 independent add2 chains in flight.
__global__ void __launch_bounds__(FTPB, 1) ffprod_k() {
    int q   = blockIdx.x;            // batches q*8 .. q*8+7
    int tau = blockIdx.y;            // column tile
    int w    = threadIdx.x >> 5;
    int lane = threadIdx.x & 31;
    const char* __restrict__ Wc =
        (const char*)d_WFsc + (size_t)(tau * FCOLS + lane * 2) * 4;
#pragma unroll 1
    for (int ti = 0; ti < 11; ti++) {            // ceil(256/24) chunks
        int t = ti * 24 + w;
        if (t < TT) {
#pragma unroll 1
            for (int bi = 0; bi < 8; bi++) {
                int b  = q * 8 + bi;
                int bt = b * TT + t;
                int fc = d_ffcnt[bt];
                const int* __restrict__ lst = d_fflist[bt];
                u64 a0 = 0ull, a1 = 0ull, a2 = 0ull, a3 = 0ull;
                for (int base = 0; base < fc; base += 32) {
                    int rem = fc - base; if (rem > 32) rem = 32;
                    int myo = (lane < rem) ? lst[base + lane] : 0;
                    int j = 0;
#pragma unroll 2
                    for (; j + 3 < rem; j += 4) {
                        int o0 = __shfl_sync(0xFFFFFFFFu, myo, j);
                        int o1 = __shfl_sync(0xFFFFFFFFu, myo, j + 1);
                        int o2 = __shfl_sync(0xFFFFFFFFu, myo, j + 2);
                        int o3 = __shfl_sync(0xFFFFFFFFu, myo, j + 3);
                        a0 = add2(a0, *(const u64*)(Wc + o0));
                        a1 = add2(a1, *(const u64*)(Wc + o1));
                        a2 = add2(a2, *(const u64*)(Wc + o2));
                        a3 = add2(a3, *(const u64*)(Wc + o3));
                    }
                    for (; j < rem; j++) {
                        int o0 = __shfl_sync(0xFFFFFFFFu, myo, j);
                        a0 = add2(a0, *(const u64*)(Wc + o0));
                    }
                }
                u64 s = add2(add2(a0, a2), add2(a1, a3));
                float lo, hi;
                upk2(lo, hi, s);
                *(float2*)&d_IF[(size_t)bt * NN + tau * FCOLS + lane * 2] =
                    make_float2(lo, hi);
            }
        }
        __syncthreads();                 // all rows of this chunk written
        if (threadIdx.x < 8) {
            __threadfence();             // publish
            int wmv = (ti + 1) * 24; if (wmv > TT) wmv = TT;
            __stcg(&d_wm[q * 8 + threadIdx.x][tau], wmv);
        }
    }
}

// ------------------------- main persistent simulator ------------------------
// grid = 32 (one CTA per batch), block = 384 (one thread per 4 neurons).
// Runs CONCURRENTLY with ffprod_k; consumes d_IF guarded by watermarks,
// polled once per 16 steps (24 threads in parallel). Spike exchange: flat
// 48-word sorted bitmask + 2 summary words, sparse atomicOr, triple-buffered,
// ONE barrier per step.
__global__ void __launch_bounds__(TPB, 1)
sim_k(const int* __restrict__ ct, float* __restrict__ out) {
    const int b    = blockIdx.x;
    const int tid  = threadIdx.x;
    const int n0   = tid * NPT;

    __shared__ unsigned smask[3][NWORD];        // spike bits (sorted rows)
    __shared__ unsigned ssum[3][2];             // summary: word w nonzero

    if (tid < 3 * NWORD) ((unsigned*)smask)[tid] = 0;
    if (tid < 6)         ((unsigned*)ssum)[tid]  = 0;

    int4 ctv = *(const int4*)(ct + n0);
    const int ctk[NPT] = {ctv.x, ctv.y, ctv.z, ctv.w};
    int4 pv = *(const int4*)(d_perm + n0);
    const int pk[NPT] = {pv.x, pv.y, pv.z, pv.w};
    const int NA = d_NA;

    float leak[NPT], refstep[NPT];
#pragma unroll
    for (int k = 0; k < NPT; k++) {
        leak[k]    = ctk[k] ? 0.01f : 0.005f;
        refstep[k] = ctk[k] ? 1.0f : 2.0f;
    }
    const u64 leakp[2] = {pk2(leak[0], leak[1]), pk2(leak[2], leak[3])};

    const u64 AR0p = pk2(AR0, AR0), AR1p = pk2(AR1, AR1);
    const u64 AD0p = pk2(AD0, AD0), AD1p = pk2(AD1, AD1), AD2p = pk2(AD2, AD2);
    const u64 HALFp = pk2(0.5f, 0.5f), M70p = pk2(-70.f, -70.f);
    const u64 M65p  = pk2(-65.f, -65.f), TENp = pk2(10.f, 10.f);

    u64 X0[2], X1[2], X2[2], G0[2], G1[2], G2[2], XF[2], GF[2];
    float U[NPT], ref[NPT];
#pragma unroll
    for (int p = 0; p < 2; p++)
        X0[p] = X1[p] = X2[p] = G0[p] = G1[p] = G2[p] = XF[p] = GF[p] = 0ull;
#pragma unroll
    for (int k = 0; k < NPT; k++) { U[k] = -65.0f; ref[k] = 0.f; }

    const char* __restrict__ wb   = (const char*)d_Wsc + (size_t)n0 * 4;
    const float* __restrict__ ifp = d_IF + (size_t)b * TT * NN + n0;
    const size_t VOFF = (size_t)BB * TT * NN;

    // wait for FF rows 0..16 (steps 0..15 prefetch up to row 16); acquire
    if (tid < NTILE) {
        while (__ldcg(&d_wm[b][tid]) < 17) __nanosleep(128);
        __threadfence();
    }
    __syncthreads();                           // smem init + FF rows visible

    float4 ffcur = __ldcg((const float4*)ifp); // FF drive for t=0

    int cur = 0, rp = 2, nxt = 1;              // t=0 phases

    for (int t = 0; t < TT; t++) {
        // prefetch FF drive for t+1 (readiness guaranteed by watermarks)
        float4 ffnext = (t + 1 < TT)
            ? __ldcg((const float4*)(ifp + (size_t)(t + 1) * NN))
            : make_float4(0.f, 0.f, 0.f, 0.f);

        // zero the buffer that will be written at t+1 (last read at t-1)
        if (tid < NWORD + 2) {
            if (tid < NWORD) smask[nxt][tid] = 0;
            else             ssum[nxt][tid - NWORD] = 0;
        }

        // -------- sparse recurrent gather via flat sorted bitmask -----------
        u64 aA01 = 0ull, aA23 = 0ull, aB01 = 0ull, aB23 = 0ull;
        {
            uint2 sv2 = *(const uint2*)&ssum[rp][0];
            unsigned sw[2] = {sv2.x, sv2.y};
#pragma unroll
            for (int h = 0; h < 2; h++) {
                unsigned s = sw[h];
                while (s) {
                    int wbit = __ffs(s) - 1; s &= s - 1;
                    int word = h * 32 + wbit;
                    unsigned m = smask[rp][word];
                    int dlt = NA - (word << 5);
                    unsigned aM = (dlt <= 0) ? 0u
                                : ((dlt >= 32) ? 0xFFFFFFFFu
                                               : ((1u << dlt) - 1u));
                    unsigned mA = m & aM, mB = m & ~aM;
                    const char* base = wb + (size_t)(word << 5) * (NN * 4);
                    while (mA) {
                        int i = __ffs(mA) - 1; mA &= mA - 1;
                        ulonglong2 ww = *(const ulonglong2*)(base + i * (NN * 4));
                        aA01 = add2(aA01, ww.x);
                        aA23 = add2(aA23, ww.y);
                    }
                    while (mB) {
                        int i = __ffs(mB) - 1; mB &= mB - 1;
                        ulonglong2 ww = *(const ulonglong2*)(base + i * (NN * 4));
                        aB01 = add2(aB01, ww.x);
                        aB23 = add2(aB23, ww.y);
                    }
                }
            }
        }
        const u64 inAp[2] = {aA01, aA23};
        const u64 inBp[2] = {aB01, aB23};
        const u64 inFp[2] = {pk2(ffcur.x, ffcur.y), pk2(ffcur.z, ffcur.w)};
        ffcur = ffnext;

        // -------- neuron update (packed filters + membrane) ----------------
        float sv[NPT], uv[NPT];
#pragma unroll
        for (int p = 0; p < 2; p++) {
            X0[p] = fma2(AR0p, X0[p], inAp[p]);
            X1[p] = fma2(AR1p, X1[p], inAp[p]);
            X2[p] = fma2(AR0p, X2[p], inBp[p]);
            G0[p] = fma2(AD0p, G0[p], X0[p]);
            G1[p] = fma2(AD1p, G1[p], X1[p]);
            G2[p] = fma2(AD2p, G2[p], X2[p]);
            XF[p] = fma2(AR0p, XF[p], inFp[p]);
            GF[p] = fma2(AD0p, GF[p], XF[p]);

            u64 gtot = add2(fma2(HALFp, G1[p], G0[p]), add2(G2[p], GF[p]));
            u64 gE   = mul2(M70p, G2[p]);
            float u0 = U[p * 2], u1 = U[p * 2 + 1];
            u64 Up  = pk2(u0, u1);
            u64 nUp = pk2(-u0, -u1);
            u64 Isyn = fma2(gtot, nUp, gE);
            u64 s1   = add2(M65p, nUp);
            u64 s2   = fma2(TENp, s1, Isyn);
            u64 Unp  = fma2(leakp[p], s2, Up);

            float Un0, Un1;
            upk2(Un0, Un1, Unp);
            float Unk[2] = {Un0, Un1};
#pragma unroll
            for (int q = 0; q < 2; q++) {
                int k = p * 2 + q;
                float Un = Unk[q];
                if (ref[k] > 0.0f) Un = -65.0f;      // refractory clamp
                ref[k] = fmaxf(ref[k] - 1.0f, 0.0f);
                float s = ((Un + 50.0f) >= 0.0f) ? 1.0f : 0.0f;
                if (s > 0.0f) { Un = -65.0f; ref[k] = refstep[k]; }
                U[k] = Un;
                sv[k] = s;
                uv[k] = Un;
            }
        }

        // -------- spike publication (sparse atomicOr, deterministic) -------
#pragma unroll
        for (int k = 0; k < NPT; k++) {
            if (sv[k] > 0.0f) {
                int p = pk[k];
                atomicOr(&smask[cur][p >> 5], 1u << (p & 31));
                if (p < 1024) atomicOr(&ssum[cur][0], 1u << (p >> 5));
                else          atomicOr(&ssum[cur][1], 1u << ((p >> 5) - 32));
            }
        }

        // outputs: spikes then volts, both (B,T,N)
        size_t o = ((size_t)b * TT + t) * NN + n0;
        *(float4*)(out + o)        = make_float4(sv[0], sv[1], sv[2], sv[3]);
        *(float4*)(out + VOFF + o) = make_float4(uv[0], uv[1], uv[2], uv[3]);

        // -------- periodic FF watermark poll (covers next 16 steps) --------
        if ((t & 15) == 15 && t < TT - 1 && tid < NTILE) {
            int target = t + 18; if (target > TT) target = TT;
            while (__ldcg(&d_wm[b][tid]) < target) __nanosleep(128);
            __threadfence();
        }

        // rotate triple-buffer phases
        int tmp = rp; rp = cur; cur = nxt; nxt = tmp;
        __syncthreads();                       // the ONE barrier per step
    }
}

// ------------------------- launcher (forked capture branches) ---------------
extern "C" void kernel_launch(void* const* d_in, const int* in_sizes, int n_in,
                              void* d_out, int out_size) {
    const float* input_spikes = (const float*)d_in[0]; // (B,T,NI)
    const float* weights      = (const float*)d_in[1]; // (NN,NN)
    const float* weights_FF   = (const float*)d_in[2]; // (NI,NN)
    const float* sf           = (const float*)d_in[3]; // (2,2)
    const float* sff          = (const float*)d_in[4]; // (1,2)
    const int*   ct           = (const int*)d_in[5];   // (NN,)
    (void)in_sizes; (void)n_in; (void)out_size;

    // persistent side-stream + fork/join events (host objects; created once)
    static cudaStream_t s2 = nullptr;
    static cudaEvent_t evFork = nullptr, evJoin = nullptr;
    if (s2 == nullptr) {
        cudaStreamCreateWithFlags(&s2, cudaStreamNonBlocking);
        cudaEventCreateWithFlags(&evFork, cudaEventDisableTiming);
        cudaEventCreateWithFlags(&evJoin, cudaEventDisableTiming);
    }

    // prologue: permutation + watermark reset (needed by BOTH branches)
    perm_k<<<1, 256>>>(ct);

    // fork right after perm: side stream does FF prep + producer
    cudaEventRecord(evFork, 0);
    cudaStreamWaitEvent(s2, evFork, 0);
    scaleWF_k<<<(NI * NN / 4 + 255) / 256, 256, 0, s2>>>(
        (const float4*)weights_FF, sff, ct);
    ffl_k<<<BB * TT / 4, 128, 0, s2>>>(input_spikes);
    ffprod_k<<<dim3(4, NTILE), FTPB, 0, s2>>>();
    cudaEventRecord(evJoin, s2);

    // main branch: recurrent weight scaling, then the simulator
    scaleW_k<<<(NN * NN / 4 + 255) / 256, 256>>>((const float4*)weights,
                                                 sf, ct);
    sim_k<<<BB, TPB>>>(ct, (float*)d_out);

    // join
    cudaStreamWaitEvent(0, evJoin, 0);
}

// round 17
// speedup vs baseline: 1.1276x; 1.1276x over previous
#include <cuda_runtime.h>
#include <cstdint>

// Problem constants (fixed by the reference)
#define BB 32
#define TT 256
#define NN 1536
#define NI 768

// Sim config: ONE CTA per batch, 384 threads, 4 neurons/thread.
#define TPB   384
#define NPT   4
#define NWORD 48                   // 1536 spike bits = 48 words
#define NTILE 24                   // ffprod column tiles of 64
#define FCOLS 64
#define FTPB  768                  // producer threads (24 warps/SM)

// exp constants, correctly rounded fp32
#define AR0 0.13533528323661270f   // exp(-2)    : rise tau 0.5 (syn0, syn2, FF)
#define AR1 0.60653065971263342f   // exp(-0.5)  : rise tau 2   (syn1)
#define AD0 0.60653065971263342f   // exp(-0.5)  : decay tau 2  (syn0, FF)
#define AD1 0.99004983374916805f   // exp(-0.01) : decay tau 100(syn1)
#define AD2 0.81873075307798186f   // exp(-0.2)  : decay tau 5  (syn2)

// ------------------------- device scratch (statics; no allocs) -------------
__device__ float d_Wsc[NN * NN];             // scaled W, rows in SORTED order
__device__ float d_WFsc[NI * NN];            // weights_FF * sfF[ct[m]]
__device__ float d_IF[(size_t)BB * TT * NN]; // FF drive (produced concurrently)
__device__ int   d_ffcnt[BB * TT];           // input spike counts per (b,t)
__device__ int   d_fflist[BB * TT][NI];      // byte offsets j*NN*4 (16B-aligned rows)
__device__ int   d_perm[NN];                 // n -> sorted row position
__device__ int   d_NA;                       // #type-0 neurons
__device__ int   d_wm[BB][NTILE];            // FF progress watermarks (in t)

// ------------------------- packed f32x2 helpers -----------------------------
typedef unsigned long long u64;
__device__ __forceinline__ u64 pk2(float lo, float hi) {
    u64 r; asm("mov.b64 %0, {%1,%2};" : "=l"(r) : "f"(lo), "f"(hi)); return r;
}
__device__ __forceinline__ void upk2(float& lo, float& hi, u64 v) {
    asm("mov.b64 {%0,%1}, %2;" : "=f"(lo), "=f"(hi) : "l"(v));
}
__device__ __forceinline__ u64 fma2(u64 a, u64 b, u64 c) {
    u64 d; asm("fma.rn.f32x2 %0, %1, %2, %3;" : "=l"(d) : "l"(a), "l"(b), "l"(c));
    return d;
}
__device__ __forceinline__ u64 add2(u64 a, u64 b) {
    u64 d; asm("add.rn.f32x2 %0, %1, %2;" : "=l"(d) : "l"(a), "l"(b)); return d;
}
__device__ __forceinline__ u64 mul2(u64 a, u64 b) {
    u64 d; asm("mul.rn.f32x2 %0, %1, %2;" : "=l"(d) : "l"(a), "l"(b)); return d;
}

// --------- permutation (warp 0) + watermark reset, 256 threads --------------
// msave[48] costs ~100 regs/thread: keep the block at 256 threads MAX
// (768-thread launches of this kernel exceed the register file: rounds 13/14).
__global__ void __launch_bounds__(256) perm_k(const int* __restrict__ ct) {
    int tid = threadIdx.x;
    for (int i = tid; i < BB * NTILE; i += 256) ((int*)d_wm)[i] = 0;
    if (tid >= 32) return;                          // warp 0: permutation
    int lane = tid;
    unsigned lt = (1u << lane) - 1u;
    unsigned msave[NWORD];
    int NAtot = 0;
#pragma unroll
    for (int w = 0; w < NWORD; w++) {
        int c = ct[w * 32 + lane];
        unsigned m = __ballot_sync(0xFFFFFFFFu, c == 0);
        msave[w] = m;
        NAtot += __popc(m);
    }
    int cA = 0, cB = 0;
#pragma unroll
    for (int w = 0; w < NWORD; w++) {
        unsigned m = msave[w];
        int is0 = (m >> lane) & 1;
        int p = is0 ? (cA + __popc(m & lt))
                    : (NAtot + cB + __popc((~m) & lt));
        d_perm[w * 32 + lane] = p;
        cA += __popc(m);
        cB += 32 - __popc(m);
    }
    if (lane == 0) d_NA = NAtot;
}

// ------------------------- FF weight scaling ---------------------------------
__global__ void scaleWF_k(const float4* __restrict__ wff,
                          const float* __restrict__ sff,
                          const int* __restrict__ ct) {
    const int F4 = (NI * NN) / 4;
    int r = blockIdx.x * 256 + threadIdx.x;
    if (r < F4) {
        int i4 = r * 4;
        int m = i4 % NN;
        int4 cm = *(const int4*)(ct + m);
        float4 v = wff[r];
        v.x *= sff[cm.x];
        v.y *= sff[cm.y];
        v.z *= sff[cm.z];
        v.w *= sff[cm.w];
        *(float4*)&d_WFsc[i4] = v;
    }
}

// ------------------------- recurrent weight scaling (rows permuted) --------
__global__ void scaleW_k(const float4* __restrict__ w,
                         const float* __restrict__ sf,
                         const int* __restrict__ ct) {
    const int T4 = (NN * NN) / 4;
    int idx = blockIdx.x * 256 + threadIdx.x;
    if (idx < T4) {
        int i4 = idx * 4;
        int n = i4 / NN, m = i4 % NN;
        int4 cm = *(const int4*)(ct + m);
        int cn = ct[n] * 2;
        float4 v = w[idx];
        v.x *= sf[cn + cm.x];
        v.y *= sf[cn + cm.y];
        v.z *= sf[cn + cm.z];
        v.w *= sf[cn + cm.w];
        int pn = d_perm[n];                       // sorted row placement
        *(float4*)&d_Wsc[pn * NN + m] = v;
    }
}

// ------------------------- FF spike lists (ballot-ordered, byte offsets) ---
__global__ void ffl_k(const float* __restrict__ inp) {
    int bt = blockIdx.x * 4 + (threadIdx.x >> 5); // 4 (b,t) rows per block
    int lane = threadIdx.x & 31;
    const float* row = inp + (size_t)bt * NI;
    int cnt = 0;
    for (int base = 0; base < NI; base += 32) {
        float v = row[base + lane];
        unsigned m = __ballot_sync(0xFFFFFFFFu, v > 0.5f);
        if (v > 0.5f) {
            int p = cnt + __popc(m & ((1u << lane) - 1u));
            d_fflist[bt][p] = (base + lane) * NN * 4;   // byte offset of row
        }
        cnt += __popc(m);
    }
    if (lane == 0) d_ffcnt[bt] = cnt;
}

// ------------------------- FF drive producer (1 CTA per SM, 1 tile) ---------
// Grid = (batch-octet 0..3, tile 0..23) = 96 CTAs; with 32 sim CTAs = 128
// <= 148 SMs -> one CTA per SM, each owning ONE 196KB L1-resident slab.
// List offsets are read 4-at-a-time via LDG.128 (rows are 16B-aligned) and
// feed 4 independent add2 chains -> up to 16 weight loads in flight per warp.
__global__ void __launch_bounds__(FTPB, 1) ffprod_k() {
    int q   = blockIdx.x;            // batches q*8 .. q*8+7
    int tau = blockIdx.y;            // column tile
    int w    = threadIdx.x >> 5;
    int lane = threadIdx.x & 31;
    const char* __restrict__ Wc =
        (const char*)d_WFsc + (size_t)(tau * FCOLS + lane * 2) * 4;
#pragma unroll 1
    for (int ti = 0; ti < 11; ti++) {            // ceil(256/24) chunks
        int t = ti * 24 + w;
        if (t < TT) {
#pragma unroll 1
            for (int bi = 0; bi < 8; bi++) {
                int b  = q * 8 + bi;
                int bt = b * TT + t;
                int fc = d_ffcnt[bt];
                const int4* __restrict__ l4 = (const int4*)d_fflist[bt];
                u64 a0 = 0ull, a1 = 0ull, a2 = 0ull, a3 = 0ull;
                int fc4 = fc >> 2;
#pragma unroll 4
                for (int i = 0; i < fc4; i++) {
                    int4 o = l4[i];
                    a0 = add2(a0, *(const u64*)(Wc + o.x));
                    a1 = add2(a1, *(const u64*)(Wc + o.y));
                    a2 = add2(a2, *(const u64*)(Wc + o.z));
                    a3 = add2(a3, *(const u64*)(Wc + o.w));
                }
                const int* __restrict__ lst = d_fflist[bt];
                for (int e = fc4 * 4; e < fc; e++)
                    a0 = add2(a0, *(const u64*)(Wc + lst[e]));
                u64 s = add2(add2(a0, a1), add2(a2, a3));
                float lo, hi;
                upk2(lo, hi, s);
                *(float2*)&d_IF[(size_t)bt * NN + tau * FCOLS + lane * 2] =
                    make_float2(lo, hi);
            }
        }
        __syncthreads();                 // all rows of this chunk written
        if (threadIdx.x < 8) {
            __threadfence();             // publish
            int wmv = (ti + 1) * 24; if (wmv > TT) wmv = TT;
            __stcg(&d_wm[q * 8 + threadIdx.x][tau], wmv);
        }
    }
}

// ------------------------- main persistent simulator ------------------------
// grid = 32 (one CTA per batch), block = 384 (one thread per 4 neurons).
// Runs CONCURRENTLY with ffprod_k; consumes d_IF guarded by watermarks,
// polled once per 16 steps (24 threads in parallel). Spike exchange: flat
// 48-word sorted bitmask + 2 summary words, sparse atomicOr, triple-buffered,
// ONE barrier per step.
__global__ void __launch_bounds__(TPB, 1)
sim_k(const int* __restrict__ ct, float* __restrict__ out) {
    const int b    = blockIdx.x;
    const int tid  = threadIdx.x;
    const int n0   = tid * NPT;

    __shared__ unsigned smask[3][NWORD];        // spike bits (sorted rows)
    __shared__ unsigned ssum[3][2];             // summary: word w nonzero

    if (tid < 3 * NWORD) ((unsigned*)smask)[tid] = 0;
    if (tid < 6)         ((unsigned*)ssum)[tid]  = 0;

    int4 ctv = *(const int4*)(ct + n0);
    const int ctk[NPT] = {ctv.x, ctv.y, ctv.z, ctv.w};
    int4 pv = *(const int4*)(d_perm + n0);
    const int pk[NPT] = {pv.x, pv.y, pv.z, pv.w};
    const int NA = d_NA;

    float leak[NPT], refstep[NPT];
#pragma unroll
    for (int k = 0; k < NPT; k++) {
        leak[k]    = ctk[k] ? 0.01f : 0.005f;
        refstep[k] = ctk[k] ? 1.0f : 2.0f;
    }
    const u64 leakp[2] = {pk2(leak[0], leak[1]), pk2(leak[2], leak[3])};

    const u64 AR0p = pk2(AR0, AR0), AR1p = pk2(AR1, AR1);
    const u64 AD0p = pk2(AD0, AD0), AD1p = pk2(AD1, AD1), AD2p = pk2(AD2, AD2);
    const u64 HALFp = pk2(0.5f, 0.5f), M70p = pk2(-70.f, -70.f);
    const u64 M65p  = pk2(-65.f, -65.f), TENp = pk2(10.f, 10.f);

    u64 X0[2], X1[2], X2[2], G0[2], G1[2], G2[2], XF[2], GF[2];
    float U[NPT], ref[NPT];
#pragma unroll
    for (int p = 0; p < 2; p++)
        X0[p] = X1[p] = X2[p] = G0[p] = G1[p] = G2[p] = XF[p] = GF[p] = 0ull;
#pragma unroll
    for (int k = 0; k < NPT; k++) { U[k] = -65.0f; ref[k] = 0.f; }

    const char* __restrict__ wb   = (const char*)d_Wsc + (size_t)n0 * 4;
    const float* __restrict__ ifp = d_IF + (size_t)b * TT * NN + n0;
    const size_t VOFF = (size_t)BB * TT * NN;

    // wait for FF rows 0..16 (steps 0..15 prefetch up to row 16); acquire
    if (tid < NTILE) {
        while (__ldcg(&d_wm[b][tid]) < 17) __nanosleep(128);
        __threadfence();
    }
    __syncthreads();                           // smem init + FF rows visible

    float4 ffcur = __ldcg((const float4*)ifp); // FF drive for t=0

    int cur = 0, rp = 2, nxt = 1;              // t=0 phases

    for (int t = 0; t < TT; t++) {
        // prefetch FF drive for t+1 (readiness guaranteed by watermarks)
        float4 ffnext = (t + 1 < TT)
            ? __ldcg((const float4*)(ifp + (size_t)(t + 1) * NN))
            : make_float4(0.f, 0.f, 0.f, 0.f);

        // zero the buffer that will be written at t+1 (last read at t-1)
        if (tid < NWORD + 2) {
            if (tid < NWORD) smask[nxt][tid] = 0;
            else             ssum[nxt][tid - NWORD] = 0;
        }

        // -------- sparse recurrent gather via flat sorted bitmask -----------
        u64 aA01 = 0ull, aA23 = 0ull, aB01 = 0ull, aB23 = 0ull;
        {
            uint2 sv2 = *(const uint2*)&ssum[rp][0];
            unsigned sw[2] = {sv2.x, sv2.y};
#pragma unroll
            for (int h = 0; h < 2; h++) {
                unsigned s = sw[h];
                while (s) {
                    int wbit = __ffs(s) - 1; s &= s - 1;
                    int word = h * 32 + wbit;
                    unsigned m = smask[rp][word];
                    int dlt = NA - (word << 5);
                    unsigned aM = (dlt <= 0) ? 0u
                                : ((dlt >= 32) ? 0xFFFFFFFFu
                                               : ((1u << dlt) - 1u));
                    unsigned mA = m & aM, mB = m & ~aM;
                    const char* base = wb + (size_t)(word << 5) * (NN * 4);
                    while (mA) {
                        int i = __ffs(mA) - 1; mA &= mA - 1;
                        ulonglong2 ww = *(const ulonglong2*)(base + i * (NN * 4));
                        aA01 = add2(aA01, ww.x);
                        aA23 = add2(aA23, ww.y);
                    }
                    while (mB) {
                        int i = __ffs(mB) - 1; mB &= mB - 1;
                        ulonglong2 ww = *(const ulonglong2*)(base + i * (NN * 4));
                        aB01 = add2(aB01, ww.x);
                        aB23 = add2(aB23, ww.y);
                    }
                }
            }
        }
        const u64 inAp[2] = {aA01, aA23};
        const u64 inBp[2] = {aB01, aB23};
        const u64 inFp[2] = {pk2(ffcur.x, ffcur.y), pk2(ffcur.z, ffcur.w)};
        ffcur = ffnext;

        // -------- neuron update (packed filters + membrane) ----------------
        float sv[NPT], uv[NPT];
#pragma unroll
        for (int p = 0; p < 2; p++) {
            X0[p] = fma2(AR0p, X0[p], inAp[p]);
            X1[p] = fma2(AR1p, X1[p], inAp[p]);
            X2[p] = fma2(AR0p, X2[p], inBp[p]);
            G0[p] = fma2(AD0p, G0[p], X0[p]);
            G1[p] = fma2(AD1p, G1[p], X1[p]);
            G2[p] = fma2(AD2p, G2[p], X2[p]);
            XF[p] = fma2(AR0p, XF[p], inFp[p]);
            GF[p] = fma2(AD0p, GF[p], XF[p]);

            u64 gtot = add2(fma2(HALFp, G1[p], G0[p]), add2(G2[p], GF[p]));
            u64 gE   = mul2(M70p, G2[p]);
            float u0 = U[p * 2], u1 = U[p * 2 + 1];
            u64 Up  = pk2(u0, u1);
            u64 nUp = pk2(-u0, -u1);
            u64 Isyn = fma2(gtot, nUp, gE);
            u64 s1   = add2(M65p, nUp);
            u64 s2   = fma2(TENp, s1, Isyn);
            u64 Unp  = fma2(leakp[p], s2, Up);

            float Un0, Un1;
            upk2(Un0, Un1, Unp);
            float Unk[2] = {Un0, Un1};
#pragma unroll
            for (int q = 0; q < 2; q++) {
                int k = p * 2 + q;
                float Un = Unk[q];
                if (ref[k] > 0.0f) Un = -65.0f;      // refractory clamp
                ref[k] = fmaxf(ref[k] - 1.0f, 0.0f);
                float s = ((Un + 50.0f) >= 0.0f) ? 1.0f : 0.0f;
                if (s > 0.0f) { Un = -65.0f; ref[k] = refstep[k]; }
                U[k] = Un;
                sv[k] = s;
                uv[k] = Un;
            }
        }

        // -------- spike publication (sparse atomicOr, deterministic) -------
#pragma unroll
        for (int k = 0; k < NPT; k++) {
            if (sv[k] > 0.0f) {
                int p = pk[k];
                atomicOr(&smask[cur][p >> 5], 1u << (p & 31));
                if (p < 1024) atomicOr(&ssum[cur][0], 1u << (p >> 5));
                else          atomicOr(&ssum[cur][1], 1u << ((p >> 5) - 32));
            }
        }

        // outputs: spikes then volts, both (B,T,N)
        size_t o = ((size_t)b * TT + t) * NN + n0;
        *(float4*)(out + o)        = make_float4(sv[0], sv[1], sv[2], sv[3]);
        *(float4*)(out + VOFF + o) = make_float4(uv[0], uv[1], uv[2], uv[3]);

        // -------- periodic FF watermark poll (covers next 16 steps) --------
        if ((t & 15) == 15 && t < TT - 1 && tid < NTILE) {
            int target = t + 18; if (target > TT) target = TT;
            while (__ldcg(&d_wm[b][tid]) < target) __nanosleep(128);
            __threadfence();
        }

        // rotate triple-buffer phases
        int tmp = rp; rp = cur; cur = nxt; nxt = tmp;
        __syncthreads();                       // the ONE barrier per step
    }
}

// ------------------------- launcher (forked capture branches) ---------------
extern "C" void kernel_launch(void* const* d_in, const int* in_sizes, int n_in,
                              void* d_out, int out_size) {
    const float* input_spikes = (const float*)d_in[0]; // (B,T,NI)
    const float* weights      = (const float*)d_in[1]; // (NN,NN)
    const float* weights_FF   = (const float*)d_in[2]; // (NI,NN)
    const float* sf           = (const float*)d_in[3]; // (2,2)
    const float* sff          = (const float*)d_in[4]; // (1,2)
    const int*   ct           = (const int*)d_in[5];   // (NN,)
    (void)in_sizes; (void)n_in; (void)out_size;

    // persistent side-stream + fork/join events (host objects; created once)
    static cudaStream_t s2 = nullptr;
    static cudaEvent_t evFork = nullptr, evJoin = nullptr;
    if (s2 == nullptr) {
        cudaStreamCreateWithFlags(&s2, cudaStreamNonBlocking);
        cudaEventCreateWithFlags(&evFork, cudaEventDisableTiming);
        cudaEventCreateWithFlags(&evJoin, cudaEventDisableTiming);
    }

    // prologue: permutation + watermark reset (needed by BOTH branches)
    perm_k<<<1, 256>>>(ct);

    // fork right after perm: side stream does FF prep + producer
    cudaEventRecord(evFork, 0);
    cudaStreamWaitEvent(s2, evFork, 0);
    scaleWF_k<<<(NI * NN / 4 + 255) / 256, 256, 0, s2>>>(
        (const float4*)weights_FF, sff, ct);
    ffl_k<<<BB * TT / 4, 128, 0, s2>>>(input_spikes);
    ffprod_k<<<dim3(4, NTILE), FTPB, 0, s2>>>();
    cudaEventRecord(evJoin, s2);

    // main branch: recurrent weight scaling, then the simulator
    scaleW_k<<<(NN * NN / 4 + 255) / 256, 256>>>((const float4*)weights,
                                                 sf, ct);
    sim_k<<<BB, TPB>>>(ct, (float*)d_out);

    // join
    cudaStreamWaitEvent(0, evJoin, 0);
}